// round 1
// baseline (speedup 1.0000x reference)
#include <cuda_runtime.h>
#include <math.h>

// Problem constants
#define BATCH 64
#define H 224
#define W 224
#define CH 3
#define FEAT_H 5
#define FEAT_W 5

// Scratch (device globals — no allocation allowed)
__device__ float g_planes[CH][BATCH * H * W];        // channel-deinterleaved input
__device__ float g_feat[BATCH * FEAT_H * FEAT_W * CH]; // (B,5,5,3) feature map

// ---------------------------------------------------------------------------
// Kernel 1: NHWC -> 3 channel planes (coalesced read; near-coalesced writes)
// ---------------------------------------------------------------------------
__global__ void transpose_kernel(const float* __restrict__ in) {
    int idx = blockIdx.x * blockDim.x + threadIdx.x;
    const int total = BATCH * H * W * CH;
    if (idx >= total) return;
    float v = in[idx];
    int ch = idx % 3;
    int p  = idx / 3;
    g_planes[ch][p] = v;
}

// ---------------------------------------------------------------------------
// Kernel 2 (templated on K): per-(b,ch) block computes all patch stats for one
// kernel size, accumulates histogram + sums in shared memory, finalizes the
// 5 metrics and writes them into the (B,5,5,3) feature map.
// ---------------------------------------------------------------------------
template <int K>
__global__ __launch_bounds__(256) void patch_kernel() {
    constexpr int ROWS = (H + K - 1) / K;
    constexpr int COLS = (W + K - 1) / K;
    constexpr int P    = ROWS * COLS;
    constexpr int PADT = (ROWS * K - H) / 2;
    constexpr int PADL = (COLS * K - W) / 2;
    constexpr int KK   = K * K;

    const int ch = blockIdx.x;
    const int b  = blockIdx.y;
    const float* __restrict__ plane = g_planes[ch] + b * (H * W);

    __shared__ int sh_hist[KK + 1];
    __shared__ int sh_sums[3];   // ncomp, perc, marea
    for (int i = threadIdx.x; i < KK + 1; i += blockDim.x) sh_hist[i] = 0;
    if (threadIdx.x < 3) sh_sums[threadIdx.x] = 0;
    __syncthreads();

    int t_nc = 0, t_pc = 0, t_ma = 0;

    for (int pidx = threadIdx.x; pidx < P; pidx += blockDim.x) {
        const int i  = pidx / COLS;
        const int j  = pidx % COLS;
        const int r0 = i * K - PADT;
        const int c0 = j * K - PADL;

        // center pixel is always in-bounds for these geometries
        const float center = __ldg(plane + (r0 + K / 2) * W + (c0 + K / 2));

        unsigned row[K];
        int ones = 0;
        #pragma unroll
        for (int dy = 0; dy < K; dy++) {
            const int r = r0 + dy;
            unsigned m = 0;
            #pragma unroll
            for (int dx = 0; dx < K; dx++) {
                const int c = c0 + dx;
                float v = ((unsigned)r < (unsigned)H && (unsigned)c < (unsigned)W)
                              ? __ldg(plane + r * W + c) : 0.0f;
                if (fabsf(v - center) <= (float)K) m |= (1u << dx);
            }
            row[dy] = m;
            ones += __popc(m);
        }

        // Exact 4-connected components via bit-parallel flood fill.
        int ncomp = 0;
        int maxc  = KK - ones;   // background label count
        unsigned rem[K];
        #pragma unroll
        for (int r = 0; r < K; r++) rem[r] = row[r];

        while (true) {
            // find first row with a remaining set bit (unrolled -> registers)
            int sr = -1;
            #pragma unroll
            for (int r = 0; r < K; r++)
                if (sr < 0 && rem[r]) sr = r;
            if (sr < 0) break;

            unsigned cur[K];
            #pragma unroll
            for (int r = 0; r < K; r++)
                cur[r] = (r == sr) ? (rem[r] & (0u - rem[r])) : 0u;

            // grow to fixpoint (Gauss-Seidel sweep over rows)
            bool changed = true;
            while (changed) {
                changed = false;
                #pragma unroll
                for (int r = 0; r < K; r++) {
                    unsigned n = cur[r] | (cur[r] << 1) | (cur[r] >> 1);
                    if (r > 0)     n |= cur[r - 1];
                    if (r < K - 1) n |= cur[r + 1];
                    n &= rem[r];
                    if (n != cur[r]) { cur[r] = n; changed = true; }
                }
            }
            int area = 0;
            #pragma unroll
            for (int r = 0; r < K; r++) {
                area += __popc(cur[r]);
                rem[r] &= ~cur[r];
            }
            ncomp++;
            if (area > maxc) maxc = area;
        }

        atomicAdd(&sh_hist[ones], 1);
        t_nc += ncomp;
        t_pc += ((float)ones / (float)KK >= 0.59275f) ? 1 : 0;
        t_ma += maxc;
    }

    atomicAdd(&sh_sums[0], t_nc);
    atomicAdd(&sh_sums[1], t_pc);
    atomicAdd(&sh_sums[2], t_ma);
    __syncthreads();

    if (threadIdx.x == 0) {
        const float fP = (float)P;
        float fd = 0.0f, m = 0.0f, m2 = 0.0f;
        for (int q = 0; q < KK; q++) {          // bin KK (fully-on) is dropped
            float p = (float)sh_hist[q] / fP;
            float n = (float)(q + 1);
            fd += p / n;
            m  += p * n;
            m2 += p * p * n;
        }
        float lac = (m2 - m * m) / (m * m);
        int acn  = sh_sums[0] / P;              // tf integer reduce_mean
        int acp  = sh_sums[1] / P;
        int acma = sh_sums[2] / P;

        constexpr int kidx = (K - 3) / 2;
        // feat layout (b, metric_row, kidx_col, ch)
        const int base = ((b * FEAT_H) * FEAT_W + kidx) * CH + ch;
        g_feat[base + 0 * FEAT_W * CH] = (float)acn;
        g_feat[base + 1 * FEAT_W * CH] = (float)acp;
        g_feat[base + 2 * FEAT_W * CH] = (float)acma;
        g_feat[base + 3 * FEAT_W * CH] = lac;
        g_feat[base + 4 * FEAT_W * CH] = fd;
    }
}

// ---------------------------------------------------------------------------
// Kernel 3: bilinear resize (B,5,5,3) -> (B,224,224,3)
// jax.image.resize(bilinear, upsampling) == half-pixel clamp-lerp
// ---------------------------------------------------------------------------
__global__ void resize_kernel(float* __restrict__ out) {
    int idx = blockIdx.x * blockDim.x + threadIdx.x;
    const int total = BATCH * H * W * CH;
    if (idx >= total) return;

    int ch = idx % 3;
    int x  = (idx / 3) % W;
    int y  = (idx / (3 * W)) % H;
    int b  = idx / (3 * W * H);

    const float sy = (float)FEAT_H / (float)H;
    const float sx = (float)FEAT_W / (float)W;
    float cy = ((float)y + 0.5f) * sy - 0.5f;
    float cx = ((float)x + 0.5f) * sx - 0.5f;

    int y0 = (int)floorf(cy);
    int x0 = (int)floorf(cx);
    float fy = cy - (float)y0;
    float fx = cx - (float)x0;
    int y1 = y0 + 1, x1 = x0 + 1;
    y0 = min(max(y0, 0), FEAT_H - 1);
    y1 = min(max(y1, 0), FEAT_H - 1);
    x0 = min(max(x0, 0), FEAT_W - 1);
    x1 = min(max(x1, 0), FEAT_W - 1);

    const float* f = g_feat + b * (FEAT_H * FEAT_W * CH);
    float v00 = f[(y0 * FEAT_W + x0) * CH + ch];
    float v01 = f[(y0 * FEAT_W + x1) * CH + ch];
    float v10 = f[(y1 * FEAT_W + x0) * CH + ch];
    float v11 = f[(y1 * FEAT_W + x1) * CH + ch];

    out[idx] = (1.0f - fy) * ((1.0f - fx) * v00 + fx * v01)
             +          fy * ((1.0f - fx) * v10 + fx * v11);
}

// ---------------------------------------------------------------------------
extern "C" void kernel_launch(void* const* d_in, const int* in_sizes, int n_in,
                              void* d_out, int out_size) {
    const float* in = (const float*)d_in[0];
    float* out = (float*)d_out;

    const int total = BATCH * H * W * CH;
    transpose_kernel<<<(total + 255) / 256, 256>>>(in);

    dim3 grid(CH, BATCH);
    patch_kernel<3><<<grid, 256>>>();
    patch_kernel<5><<<grid, 256>>>();
    patch_kernel<7><<<grid, 256>>>();
    patch_kernel<9><<<grid, 256>>>();
    patch_kernel<11><<<grid, 256>>>();

    resize_kernel<<<(total + 255) / 256, 256>>>(out);
}

// round 2
// speedup vs baseline: 1.2428x; 1.2428x over previous
#include <cuda_runtime.h>
#include <math.h>

#define BATCH 64
#define H 224
#define W 224
#define CH 3
#define FEAT_H 5
#define FEAT_W 5
#define NPAIR (BATCH * CH)      // 192
#define ACC_STRIDE 132          // 128 hist bins + 3 sums (+1 pad)
#define ACC_INTS (5 * NPAIR * ACC_STRIDE)

// Device scratch (no allocations allowed)
__device__ float g_planes[CH][BATCH * H * W];
__device__ float g_feat[BATCH * FEAT_H * FEAT_W * CH];
__device__ int   g_acc[ACC_INTS];   // [seg][pair][bin0..127, nc, pc, ma]

// Chunks per segment (k = 3,5,7,9,11)
#define C3 22
#define C5 8
#define C7 4
#define C9 3
#define C11 2
#define OFF3 0
#define OFF5 (OFF3 + C3 * NPAIR)     // 4224
#define OFF7 (OFF5 + C5 * NPAIR)     // 5760
#define OFF9 (OFF7 + C7 * NPAIR)     // 6528
#define OFF11 (OFF9 + C9 * NPAIR)    // 7104
#define TOTAL_BLOCKS (OFF11 + C11 * NPAIR)  // 7488

// ---------------------------------------------------------------------------
// Kernel 1: NHWC -> channel planes + zero accumulators
// ---------------------------------------------------------------------------
__global__ void transpose_kernel(const float* __restrict__ in) {
    int idx = blockIdx.x * blockDim.x + threadIdx.x;
    if (idx < ACC_INTS) g_acc[idx] = 0;
    const int total = BATCH * H * W * CH;
    if (idx >= total) return;
    float v = in[idx];
    g_planes[idx % 3][idx / 3] = v;
}

// ---------------------------------------------------------------------------
// Per-segment patch body (templated on K and chunk count)
// ---------------------------------------------------------------------------
template <int K, int CHUNKS, int SEG>
__device__ __forceinline__ void patch_body(int rel, int* sh) {
    constexpr int ROWS = (H + K - 1) / K;
    constexpr int COLS = (W + K - 1) / K;
    constexpr int P    = ROWS * COLS;
    constexpr int PADT = (ROWS * K - H) / 2;
    constexpr int PADL = (COLS * K - W) / 2;
    constexpr int KK   = K * K;

    const int chunk = rel / NPAIR;
    const int pair  = rel % NPAIR;
    const int b  = pair / 3;
    const int ch = pair % 3;
    const float* __restrict__ plane = g_planes[ch] + b * (H * W);

    for (int i = threadIdx.x; i < ACC_STRIDE - 1; i += blockDim.x) sh[i] = 0;
    __syncthreads();

    int t_nc = 0, t_pc = 0, t_ma = 0;

    for (int pidx = chunk * blockDim.x + threadIdx.x; pidx < P;
         pidx += CHUNKS * blockDim.x) {
        const int i  = pidx / COLS;
        const int j  = pidx % COLS;
        const int r0 = i * K - PADT;
        const int c0 = j * K - PADL;

        const float center = __ldg(plane + (r0 + K / 2) * W + (c0 + K / 2));
        const bool interior = (r0 >= 0) & (c0 >= 0) & (r0 + K <= H) & (c0 + K <= W);

        unsigned row[K];
        int ones = 0;
        if (interior) {
            const float* base = plane + r0 * W + c0;
            #pragma unroll
            for (int dy = 0; dy < K; dy++) {
                unsigned m = 0;
                #pragma unroll
                for (int dx = 0; dx < K; dx++) {
                    float v = __ldg(base + dy * W + dx);
                    if (fabsf(v - center) <= (float)K) m |= (1u << dx);
                }
                row[dy] = m;
                ones += __popc(m);
            }
        } else {
            #pragma unroll
            for (int dy = 0; dy < K; dy++) {
                const int r = r0 + dy;
                unsigned m = 0;
                #pragma unroll
                for (int dx = 0; dx < K; dx++) {
                    const int c = c0 + dx;
                    float v = ((unsigned)r < (unsigned)H && (unsigned)c < (unsigned)W)
                                  ? __ldg(plane + r * W + c) : 0.0f;
                    if (fabsf(v - center) <= (float)K) m |= (1u << dx);
                }
                row[dy] = m;
                ones += __popc(m);
            }
        }

        // Exact 4-connected components: bit-parallel flood fill
        int ncomp = 0;
        int maxc  = KK - ones;      // background count
        unsigned rem[K];
        #pragma unroll
        for (int r = 0; r < K; r++) rem[r] = row[r];

        while (true) {
            int sr = -1;
            #pragma unroll
            for (int r = 0; r < K; r++)
                if (sr < 0 && rem[r]) sr = r;
            if (sr < 0) break;

            unsigned cur[K];
            #pragma unroll
            for (int r = 0; r < K; r++)
                cur[r] = (r == sr) ? (rem[r] & (0u - rem[r])) : 0u;

            bool changed = true;
            while (changed) {
                changed = false;
                #pragma unroll
                for (int r = 0; r < K; r++) {
                    unsigned n = cur[r] | (cur[r] << 1) | (cur[r] >> 1);
                    if (r > 0)     n |= cur[r - 1];
                    if (r < K - 1) n |= cur[r + 1];
                    n &= rem[r];
                    if (n != cur[r]) { cur[r] = n; changed = true; }
                }
            }
            int area = 0;
            #pragma unroll
            for (int r = 0; r < K; r++) {
                area += __popc(cur[r]);
                rem[r] &= ~cur[r];
            }
            ncomp++;
            if (area > maxc) maxc = area;
        }

        atomicAdd(&sh[ones], 1);
        t_nc += ncomp;
        t_pc += ((float)ones / (float)KK >= 0.59275f) ? 1 : 0;
        t_ma += maxc;
    }

    atomicAdd(&sh[128], t_nc);
    atomicAdd(&sh[129], t_pc);
    atomicAdd(&sh[130], t_ma);
    __syncthreads();

    int* dst = g_acc + (SEG * NPAIR + pair) * ACC_STRIDE;
    for (int i = threadIdx.x; i < ACC_STRIDE - 1; i += blockDim.x) {
        int v = sh[i];
        if (v) atomicAdd(&dst[i], v);
    }
}

// ---------------------------------------------------------------------------
// Kernel 2: all 5 K-sizes in one fused launch (segmented grid)
// ---------------------------------------------------------------------------
__global__ __launch_bounds__(256) void patch_all_kernel() {
    __shared__ int sh[ACC_STRIDE - 1];
    const int blk = blockIdx.x;
    if (blk < OFF5)       patch_body<3,  C3,  0>(blk - OFF3,  sh);
    else if (blk < OFF7)  patch_body<5,  C5,  1>(blk - OFF5,  sh);
    else if (blk < OFF9)  patch_body<7,  C7,  2>(blk - OFF7,  sh);
    else if (blk < OFF11) patch_body<9,  C9,  3>(blk - OFF9,  sh);
    else                  patch_body<11, C11, 4>(blk - OFF11, sh);
}

// ---------------------------------------------------------------------------
// Kernel 3: finalize metrics -> (B,5,5,3) feature map
// ---------------------------------------------------------------------------
__global__ void finalize_kernel() {
    int tid = blockIdx.x * blockDim.x + threadIdx.x;
    if (tid >= 5 * NPAIR) return;
    const int seg  = tid / NPAIR;
    const int pair = tid % NPAIR;
    const int b  = pair / 3;
    const int ch = pair % 3;

    const int K  = 3 + 2 * seg;
    const int KK = K * K;
    const int ROWS = (H + K - 1) / K;
    const int COLS = (W + K - 1) / K;
    const int P    = ROWS * COLS;

    const int* acc = g_acc + (seg * NPAIR + pair) * ACC_STRIDE;
    const float fP = (float)P;
    float fd = 0.0f, m = 0.0f, m2 = 0.0f;
    for (int q = 0; q < KK; q++) {      // bin KK (fully on) dropped, matches tf
        float p = (float)acc[q] / fP;
        float n = (float)(q + 1);
        fd += p / n;
        m  += p * n;
        m2 += p * p * n;
    }
    float lac = (m2 - m * m) / (m * m);
    int acn  = acc[128] / P;
    int acp  = acc[129] / P;
    int acma = acc[130] / P;

    const int base = ((b * FEAT_H) * FEAT_W + seg) * CH + ch;
    g_feat[base + 0 * FEAT_W * CH] = (float)acn;
    g_feat[base + 1 * FEAT_W * CH] = (float)acp;
    g_feat[base + 2 * FEAT_W * CH] = (float)acma;
    g_feat[base + 3 * FEAT_W * CH] = lac;
    g_feat[base + 4 * FEAT_W * CH] = fd;
}

// ---------------------------------------------------------------------------
// Kernel 4: bilinear resize (B,5,5,3) -> (B,224,224,3)
// ---------------------------------------------------------------------------
__global__ void resize_kernel(float* __restrict__ out) {
    int idx = blockIdx.x * blockDim.x + threadIdx.x;
    const int total = BATCH * H * W * CH;
    if (idx >= total) return;

    int ch = idx % 3;
    int x  = (idx / 3) % W;
    int y  = (idx / (3 * W)) % H;
    int b  = idx / (3 * W * H);

    const float sy = (float)FEAT_H / (float)H;
    const float sx = (float)FEAT_W / (float)W;
    float cy = ((float)y + 0.5f) * sy - 0.5f;
    float cx = ((float)x + 0.5f) * sx - 0.5f;

    int y0 = (int)floorf(cy);
    int x0 = (int)floorf(cx);
    float fy = cy - (float)y0;
    float fx = cx - (float)x0;
    int y1 = y0 + 1, x1 = x0 + 1;
    y0 = min(max(y0, 0), FEAT_H - 1);
    y1 = min(max(y1, 0), FEAT_H - 1);
    x0 = min(max(x0, 0), FEAT_W - 1);
    x1 = min(max(x1, 0), FEAT_W - 1);

    const float* f = g_feat + b * (FEAT_H * FEAT_W * CH);
    float v00 = f[(y0 * FEAT_W + x0) * CH + ch];
    float v01 = f[(y0 * FEAT_W + x1) * CH + ch];
    float v10 = f[(y1 * FEAT_W + x0) * CH + ch];
    float v11 = f[(y1 * FEAT_W + x1) * CH + ch];

    out[idx] = (1.0f - fy) * ((1.0f - fx) * v00 + fx * v01)
             +          fy * ((1.0f - fx) * v10 + fx * v11);
}

// ---------------------------------------------------------------------------
extern "C" void kernel_launch(void* const* d_in, const int* in_sizes, int n_in,
                              void* d_out, int out_size) {
    const float* in = (const float*)d_in[0];
    float* out = (float*)d_out;

    const int total = BATCH * H * W * CH;
    transpose_kernel<<<(total + 255) / 256, 256>>>(in);
    patch_all_kernel<<<TOTAL_BLOCKS, 256>>>();
    finalize_kernel<<<(5 * NPAIR + 255) / 256, 256>>>();
    resize_kernel<<<(total + 255) / 256, 256>>>(out);
}

// round 4
// speedup vs baseline: 1.7228x; 1.3862x over previous
#include <cuda_runtime.h>
#include <math.h>

typedef unsigned long long u64;

#define BATCH 64
#define H 224
#define W 224
#define CH 3
#define FEAT_H 5
#define FEAT_W 5
#define NPAIR (BATCH * CH)      // 192
#define ACC_STRIDE 132          // 128 hist bins + 3 sums (+1 pad)
#define ACC_INTS (5 * NPAIR * ACC_STRIDE)

// Device scratch (no allocations allowed)
__device__ float g_planes[CH][BATCH * H * W];
__device__ float g_feat[BATCH * FEAT_H * FEAT_W * CH];
__device__ int   g_acc[ACC_INTS];   // [seg][pair][bin0..127, nc, pc, ma]

// Chunks per segment (k = 3,5,7,9,11) — clean cumulative offsets
#define C3 22
#define C5 8
#define C7 4
#define C9 3
#define C11 2
#define OFF3  0
#define OFF5  (OFF3 + C3  * NPAIR)
#define OFF7  (OFF5 + C5  * NPAIR)
#define OFF9  (OFF7 + C7  * NPAIR)
#define OFF11 (OFF9 + C9  * NPAIR)
#define TOTAL_BLOCKS (OFF11 + C11 * NPAIR)

// Column masks for K=11 (stride 11, 128-bit mask in 2x u64)
constexpr u64 colmask_lo(int c) {
    u64 m = 0;
    for (int r = 0; r < 11; r++) { int p = r * 11 + c; if (p < 64) m |= 1ull << p; }
    return m;
}
constexpr u64 colmask_hi(int c) {
    u64 m = 0;
    for (int r = 0; r < 11; r++) { int p = r * 11 + c; if (p >= 64) m |= 1ull << (p - 64); }
    return m;
}
constexpr u64 NOTC0_LO  = ~colmask_lo(0);
constexpr u64 NOTC0_HI  = ~colmask_hi(0);
constexpr u64 NOTC10_LO = ~colmask_lo(10);
constexpr u64 NOTC10_HI = ~colmask_hi(10);

// ---------------------------------------------------------------------------
// Kernel 1: NHWC -> channel planes (float4 both sides) + zero accumulators
// ---------------------------------------------------------------------------
__global__ void transpose_kernel(const float4* __restrict__ in4) {
    int t = blockIdx.x * blockDim.x + threadIdx.x;
    if (t < ACC_INTS) g_acc[t] = 0;
    const int NT = BATCH * H * W / 4;   // 802816
    if (t >= NT) return;
    float4 f0 = in4[3 * t + 0];
    float4 f1 = in4[3 * t + 1];
    float4 f2 = in4[3 * t + 2];
    ((float4*)g_planes[0])[t] = make_float4(f0.x, f0.w, f1.z, f2.y);
    ((float4*)g_planes[1])[t] = make_float4(f0.y, f1.x, f1.w, f2.z);
    ((float4*)g_planes[2])[t] = make_float4(f0.z, f1.y, f2.x, f2.w);
}

// ---------------------------------------------------------------------------
// Patch body (templated on K); bitmask connected components
// ---------------------------------------------------------------------------
template <int K, int CHUNKS, int SEG>
__device__ __forceinline__ void patch_body(int rel, int* sh) {
    constexpr int ROWS = (H + K - 1) / K;
    constexpr int COLS = (W + K - 1) / K;
    constexpr int P    = ROWS * COLS;
    constexpr int PADT = (ROWS * K - H) / 2;
    constexpr int PADL = (COLS * K - W) / 2;
    constexpr int KK   = K * K;
    constexpr int STRIDE = (K <= 7) ? 8 : 11;
    constexpr bool WIDE  = (K > 7);

    const int chunk = rel / NPAIR;
    const int pair  = rel % NPAIR;
    const int b  = pair / 3;
    const int ch = pair % 3;
    const float* __restrict__ plane = g_planes[ch] + b * (H * W);

    for (int i = threadIdx.x; i < ACC_STRIDE - 1; i += blockDim.x) sh[i] = 0;
    __syncthreads();

    int t_nc = 0, t_pc = 0, t_ma = 0;

    for (int pidx = chunk * blockDim.x + threadIdx.x; pidx < P;
         pidx += CHUNKS * blockDim.x) {
        const int i  = pidx / COLS;
        const int j  = pidx % COLS;
        const int r0 = i * K - PADT;
        const int c0 = j * K - PADL;

        const float center = __ldg(plane + (r0 + K / 2) * W + (c0 + K / 2));
        const bool interior = (r0 >= 0) & (c0 >= 0) & (r0 + K <= H) & (c0 + K <= W);

        u64 mlo = 0, mhi = 0;
        if (interior) {
            const float* base = plane + r0 * W + c0;
            #pragma unroll
            for (int dy = 0; dy < K; dy++) {
                unsigned m = 0;
                #pragma unroll
                for (int dx = 0; dx < K; dx++) {
                    float v = __ldg(base + dy * W + dx);
                    if (fabsf(v - center) <= (float)K) m |= (1u << dx);
                }
                int p = dy * STRIDE;
                if (p < 64) {
                    mlo |= (u64)m << p;
                    if (p + K > 64) mhi |= (u64)m >> (64 - p);
                } else {
                    mhi |= (u64)m << (p - 64);
                }
            }
        } else {
            #pragma unroll
            for (int dy = 0; dy < K; dy++) {
                const int r = r0 + dy;
                unsigned m = 0;
                #pragma unroll
                for (int dx = 0; dx < K; dx++) {
                    const int c = c0 + dx;
                    float v = ((unsigned)r < (unsigned)H && (unsigned)c < (unsigned)W)
                                  ? __ldg(plane + r * W + c) : 0.0f;
                    if (fabsf(v - center) <= (float)K) m |= (1u << dx);
                }
                int p = dy * STRIDE;
                if (p < 64) {
                    mlo |= (u64)m << p;
                    if (p + K > 64) mhi |= (u64)m >> (64 - p);
                } else {
                    mhi |= (u64)m << (p - 64);
                }
            }
        }

        const int ones = __popcll(mlo) + __popcll(mhi);

        int nc, ma;
        if (ones == 1) {
            nc = 1; ma = KK - 1;
        } else if (!WIDE && ones == 2) {
            u64 adj = (mlo & (mlo >> 1)) | (mlo & (mlo >> 8));
            nc = adj ? 1 : 2;
            ma = KK - 2;
        } else if (!WIDE) {
            u64 rem = mlo;
            nc = 0;
            int best = 0;
            while (rem) {
                u64 cur = rem & (~rem + 1ull);
                while (true) {
                    u64 g = (cur | (cur << 1) | (cur >> 1) | (cur << 8) | (cur >> 8)) & rem;
                    if (g == cur) break;
                    cur = g;
                }
                int a = __popcll(cur);
                if (a > best) best = a;
                rem ^= cur;
                nc++;
            }
            ma = best > (KK - ones) ? best : (KK - ones);
        } else {
            u64 rlo = mlo, rhi = mhi;
            nc = 0;
            int best = 0;
            while (rlo | rhi) {
                u64 clo, chi;
                if (rlo) { clo = rlo & (~rlo + 1ull); chi = 0; }
                else     { clo = 0; chi = rhi & (~rhi + 1ull); }
                while (true) {
                    u64 l1lo = clo << 1;
                    u64 l1hi = (chi << 1) | (clo >> 63);
                    u64 r1lo = (clo >> 1) | (chi << 63);
                    u64 r1hi = chi >> 1;
                    if (K == 11) {
                        l1lo &= NOTC0_LO;  l1hi &= NOTC0_HI;
                        r1lo &= NOTC10_LO; r1hi &= NOTC10_HI;
                    }
                    u64 uplo = clo << 11;
                    u64 uphi = (chi << 11) | (clo >> 53);
                    u64 dnlo = (clo >> 11) | (chi << 53);
                    u64 dnhi = chi >> 11;
                    u64 glo = (clo | l1lo | r1lo | uplo | dnlo) & rlo;
                    u64 ghi = (chi | l1hi | r1hi | uphi | dnhi) & rhi;
                    if (glo == clo && ghi == chi) break;
                    clo = glo; chi = ghi;
                }
                int a = __popcll(clo) + __popcll(chi);
                if (a > best) best = a;
                rlo ^= clo; rhi ^= chi;
                nc++;
            }
            ma = best > (KK - ones) ? best : (KK - ones);
        }

        atomicAdd(&sh[ones], 1);
        t_nc += nc;
        t_pc += ((float)ones / (float)KK >= 0.59275f) ? 1 : 0;
        t_ma += ma;
    }

    atomicAdd(&sh[128], t_nc);
    atomicAdd(&sh[129], t_pc);
    atomicAdd(&sh[130], t_ma);
    __syncthreads();

    int* dst = g_acc + (SEG * NPAIR + pair) * ACC_STRIDE;
    for (int i = threadIdx.x; i < ACC_STRIDE - 1; i += blockDim.x) {
        int v = sh[i];
        if (v) atomicAdd(&dst[i], v);
    }
}

__global__ __launch_bounds__(256) void patch_all_kernel() {
    __shared__ int sh[ACC_STRIDE - 1];
    const int blk = blockIdx.x;
    if (blk < OFF5)       patch_body<3,  C3,  0>(blk - OFF3,  sh);
    else if (blk < OFF7)  patch_body<5,  C5,  1>(blk - OFF5,  sh);
    else if (blk < OFF9)  patch_body<7,  C7,  2>(blk - OFF7,  sh);
    else if (blk < OFF11) patch_body<9,  C9,  3>(blk - OFF9,  sh);
    else                  patch_body<11, C11, 4>(blk - OFF11, sh);
}

// ---------------------------------------------------------------------------
// Kernel 3: finalize metrics -> (B,5,5,3) feature map
// ---------------------------------------------------------------------------
__global__ void finalize_kernel() {
    int tid = blockIdx.x * blockDim.x + threadIdx.x;
    if (tid >= 5 * NPAIR) return;
    const int seg  = tid / NPAIR;
    const int pair = tid % NPAIR;
    const int b  = pair / 3;
    const int ch = pair % 3;

    const int K  = 3 + 2 * seg;
    const int KK = K * K;
    const int ROWS = (H + K - 1) / K;
    const int COLS = (W + K - 1) / K;
    const int P    = ROWS * COLS;

    const int* acc = g_acc + (seg * NPAIR + pair) * ACC_STRIDE;
    const float fP = (float)P;
    float fd = 0.0f, m = 0.0f, m2 = 0.0f;
    for (int q = 0; q < KK; q++) {
        float p = (float)acc[q] / fP;
        float n = (float)(q + 1);
        fd += p / n;
        m  += p * n;
        m2 += p * p * n;
    }
    float lac = (m2 - m * m) / (m * m);
    int acn  = acc[128] / P;
    int acp  = acc[129] / P;
    int acma = acc[130] / P;

    const int base = ((b * FEAT_H) * FEAT_W + seg) * CH + ch;
    g_feat[base + 0 * FEAT_W * CH] = (float)acn;
    g_feat[base + 1 * FEAT_W * CH] = (float)acp;
    g_feat[base + 2 * FEAT_W * CH] = (float)acma;
    g_feat[base + 3 * FEAT_W * CH] = lac;
    g_feat[base + 4 * FEAT_W * CH] = fd;
}

// ---------------------------------------------------------------------------
// Kernel 4: fast bilinear resize via smem tile + pre-lerped rows
// ---------------------------------------------------------------------------
#define RCHUNK 8
#define YBLKS (H / RCHUNK)   // 28

__global__ __launch_bounds__(256) void resize_kernel(float* __restrict__ out) {
    __shared__ float feat[FEAT_H * FEAT_W * CH];       // 75
    __shared__ float hrow[FEAT_H * W * CH];            // 5*672 = 3360
    __shared__ float s_fy[RCHUNK];
    __shared__ int   s_y0[RCHUNK], s_y1[RCHUNK];       // premultiplied by 672

    const int blk = blockIdx.x;
    const int b   = blk / YBLKS;
    const int yc  = blk % YBLKS;
    const int tid = threadIdx.x;

    if (tid < 75) feat[tid] = g_feat[b * 75 + tid];
    if (tid >= 96 && tid < 96 + RCHUNK) {
        int y = yc * RCHUNK + (tid - 96);
        float cy = ((float)y + 0.5f) * ((float)FEAT_H / (float)H) - 0.5f;
        float fl = floorf(cy);
        int y0 = (int)fl;
        float fy = cy - fl;
        int y0c = max(y0, 0), y1c = min(y0 + 1, FEAT_H - 1);
        s_fy[tid - 96] = fy;
        s_y0[tid - 96] = y0c * (W * CH);
        s_y1[tid - 96] = y1c * (W * CH);
    }
    __syncthreads();

    for (int i = tid; i < FEAT_H * W * CH; i += 256) {
        int r  = i / (W * CH);
        int xc = i - r * (W * CH);
        int x  = xc / 3;
        int ch = xc - x * 3;
        float cx = ((float)x + 0.5f) * ((float)FEAT_W / (float)W) - 0.5f;
        float fl = floorf(cx);
        int x0 = (int)fl;
        float fx = cx - fl;
        int x0c = max(x0, 0), x1c = min(x0 + 1, FEAT_W - 1);
        float a  = feat[(r * FEAT_W + x0c) * CH + ch];
        float bb = feat[(r * FEAT_W + x1c) * CH + ch];
        hrow[i] = a + fx * (bb - a);
    }
    __syncthreads();

    float4* o4 = (float4*)(out + b * (H * W * CH) + yc * (RCHUNK * W * CH));
    const int N4 = RCHUNK * W * CH / 4;   // 1344
    for (int i = tid; i < N4; i += 256) {
        int e0 = 4 * i;
        float4 v;
        float* vp = (float*)&v;
        #pragma unroll
        for (int jj = 0; jj < 4; jj++) {
            int e  = e0 + jj;
            int yl = e / (W * CH);
            int xc = e - yl * (W * CH);
            float a  = hrow[s_y0[yl] + xc];
            float bb = hrow[s_y1[yl] + xc];
            vp[jj] = a + s_fy[yl] * (bb - a);
        }
        o4[i] = v;
    }
}

// ---------------------------------------------------------------------------
extern "C" void kernel_launch(void* const* d_in, const int* in_sizes, int n_in,
                              void* d_out, int out_size) {
    const float4* in4 = (const float4*)d_in[0];
    float* out = (float*)d_out;

    const int NT = BATCH * H * W / 4;   // 802816
    transpose_kernel<<<NT / 256, 256>>>(in4);
    patch_all_kernel<<<TOTAL_BLOCKS, 256>>>();
    finalize_kernel<<<(5 * NPAIR + 255) / 256, 256>>>();
    resize_kernel<<<BATCH * YBLKS, 256>>>(out);
}